// round 16
// baseline (speedup 1.0000x reference)
#include <cuda_runtime.h>
#include <cstdint>

#define BSZ 4096
#define DD  512
#define HH  1024
#define TW  16
#define NEL (BSZ * HH)

#define BM 128
#define BN 128
#define BK 16
#define TM 8
#define TN 8
#define FULLMASK 0xFFFFFFFFu

#define LIF_BLKS 4096

// ---------------------------------------------------------------------------
// Device scratch
// ---------------------------------------------------------------------------
__device__ float g_z0[NEL];           // fc1(x)
__device__ float g_c0[NEL];           // z0 @ w1in^T (time-invariant LIF1 input)
__device__ float g_v1[NEL], g_i1[NEL];
__device__ float g_v2[NEL], g_i2[NEL];
__device__ float g_w1T[HH * HH];      // w1rec^T
__device__ float g_f2T[HH * HH];      // fc2w^T
__device__ float g_w2T[HH * HH];      // w2rec^T
__device__ float g_Wc[HH * HH];       // w2in @ fc2w
__device__ float g_WcT[HH * HH];      // Wc^T
__device__ float g_bc[HH];            // w2in @ fc2b
__device__ unsigned short g_l1[2][NEL];   // parity-buffered z1 active lists
__device__ unsigned short g_l2[NEL];      // z2 active lists (in-place)
__device__ int g_c1[2][BSZ], g_c2[BSZ];
__device__ unsigned g_cnt[TW];

struct LifSmem { unsigned short la[HH]; unsigned short lb[HH]; int sw[8]; };

// ---------------------------------------------------------------------------
__global__ void init_state() {
    size_t i = (size_t)blockIdx.x * blockDim.x + threadIdx.x;
    size_t st = (size_t)gridDim.x * blockDim.x;
    for (size_t k = i; k < (size_t)NEL; k += st) {
        g_v1[k] = 0.f; g_i1[k] = 0.f; g_v2[k] = 0.f; g_i2[k] = 0.f;
    }
    for (size_t k = i; k < (size_t)BSZ; k += st) {
        g_c1[0][k] = 0; g_c1[1][k] = 0; g_c2[k] = 0;
    }
    if (i < TW) g_cnt[i] = 0u;
}

// ---------------------------------------------------------------------------
// Dense FFMA GEMM (proven): C = A @ W^T (+bias); prologue only
// ---------------------------------------------------------------------------
__global__ __launch_bounds__(256, 2)
void sgemm0(const float* __restrict__ A1, const float* __restrict__ W1,
            const float* __restrict__ bias, float* __restrict__ Cout,
            int K1, int N)
{
    __shared__ __align__(16) float As[2][BK][BM + 4];
    __shared__ __align__(16) float Bs[2][BK][BN + 4];
    const int tid = threadIdx.x, bn = blockIdx.x, bm = blockIdx.y;
    const int tx = tid & 15, ty = tid >> 4;
    const int lrow = tid >> 2, lcol = (tid & 3) << 2;

    float acc[TM][TN];
#pragma unroll
    for (int i = 0; i < TM; ++i)
#pragma unroll
        for (int j = 0; j < TN; ++j) acc[i][j] = 0.f;

    const int ntot = K1 / BK;
    float4 ra0, ra1, rb0, rb1;

    #define LDGT(kt) do {                                                      \
        const float* Ap = A1 + (size_t)(bm * BM + lrow) * K1 + (kt) * BK + lcol;\
        const float* Wp = W1 + (size_t)(bn * BN + lrow) * K1 + (kt) * BK + lcol;\
        ra0 = *(const float4*)Ap; ra1 = *(const float4*)(Ap + (size_t)64 * K1); \
        rb0 = *(const float4*)Wp; rb1 = *(const float4*)(Wp + (size_t)64 * K1); \
    } while (0)
    #define STST(buf) do {                                                     \
        As[buf][lcol+0][lrow]=ra0.x; As[buf][lcol+1][lrow]=ra0.y;              \
        As[buf][lcol+2][lrow]=ra0.z; As[buf][lcol+3][lrow]=ra0.w;              \
        As[buf][lcol+0][lrow+64]=ra1.x; As[buf][lcol+1][lrow+64]=ra1.y;        \
        As[buf][lcol+2][lrow+64]=ra1.z; As[buf][lcol+3][lrow+64]=ra1.w;        \
        Bs[buf][lcol+0][lrow]=rb0.x; Bs[buf][lcol+1][lrow]=rb0.y;              \
        Bs[buf][lcol+2][lrow]=rb0.z; Bs[buf][lcol+3][lrow]=rb0.w;              \
        Bs[buf][lcol+0][lrow+64]=rb1.x; Bs[buf][lcol+1][lrow+64]=rb1.y;        \
        Bs[buf][lcol+2][lrow+64]=rb1.z; Bs[buf][lcol+3][lrow+64]=rb1.w;        \
    } while (0)

    LDGT(0); STST(0); __syncthreads();
    for (int kt = 0; kt < ntot; ++kt) {
        const int cur = kt & 1;
        const bool more = (kt + 1 < ntot);
        if (more) LDGT(kt + 1);
#pragma unroll
        for (int k = 0; k < BK; ++k) {
            const float4 av0 = *(const float4*)&As[cur][k][ty * TM];
            const float4 av1 = *(const float4*)&As[cur][k][ty * TM + 4];
            const float4 bv0 = *(const float4*)&Bs[cur][k][tx * TN];
            const float4 bv1 = *(const float4*)&Bs[cur][k][tx * TN + 4];
            float a[TM] = {av0.x, av0.y, av0.z, av0.w, av1.x, av1.y, av1.z, av1.w};
            float b[TN] = {bv0.x, bv0.y, bv0.z, bv0.w, bv1.x, bv1.y, bv1.z, bv1.w};
#pragma unroll
            for (int i = 0; i < TM; ++i)
#pragma unroll
                for (int j = 0; j < TN; ++j) acc[i][j] += a[i] * b[j];
        }
        if (more) { STST(cur ^ 1); __syncthreads(); }
    }
    const int m0 = bm * BM + ty * TM, n0 = bn * BN + tx * TN;
#pragma unroll
    for (int i = 0; i < TM; ++i) {
        size_t row = (size_t)(m0 + i) * N + n0;
#pragma unroll
        for (int j = 0; j < TN; ++j) {
            float v = acc[i][j];
            if (bias) v += bias[n0 + j];
            Cout[row + j] = v;
        }
    }
}

// Square HxH transpose
__global__ void transpose_hh(const float* __restrict__ in, float* __restrict__ out) {
    __shared__ float t[32][33];
    int x = blockIdx.x * 32 + threadIdx.x, y = blockIdx.y * 32 + threadIdx.y;
    for (int j = 0; j < 32; j += 8)
        t[threadIdx.y + j][threadIdx.x] = in[(size_t)(y + j) * HH + x];
    __syncthreads();
    x = blockIdx.y * 32 + threadIdx.x; y = blockIdx.x * 32 + threadIdx.y;
    for (int j = 0; j < 32; j += 8)
        out[(size_t)(y + j) * HH + x] = t[threadIdx.x][threadIdx.y + j];
}

__global__ void bias_prop(const float* __restrict__ Wm, const float* __restrict__ b,
                          float* __restrict__ bo) {
    __shared__ float red[256];
    int n = blockIdx.x; float s = 0.f;
    for (int k = threadIdx.x; k < HH; k += 256) s += Wm[(size_t)n * HH + k] * b[k];
    red[threadIdx.x] = s; __syncthreads();
    for (int o = 128; o; o >>= 1) {
        if (threadIdx.x < o) red[threadIdx.x] += red[threadIdx.x + o];
        __syncthreads();
    }
    if (threadIdx.x == 0) bo[n] = red[0];
}

// ---------------------------------------------------------------------------
// Sparse accumulate: acc[j] += WT[k][col+j] over listed k ASCENDING (float4).
// Bitwise equal to dense fp32 FMA chain (z=1 adds w exactly; z=0 no-op).
// ---------------------------------------------------------------------------
__device__ __forceinline__ void sparse_accum4(float acc[4], const float* __restrict__ WT,
                                              const unsigned short* __restrict__ sl,
                                              int cnt, int col)
{
    int i = 0;
    for (; i + 4 <= cnt; i += 4) {
        const int k0 = sl[i], k1 = sl[i + 1], k2 = sl[i + 2], k3 = sl[i + 3];
        float4 a = *(const float4*)(WT + (size_t)k0 * HH + col);
        float4 b = *(const float4*)(WT + (size_t)k1 * HH + col);
        float4 c = *(const float4*)(WT + (size_t)k2 * HH + col);
        float4 d = *(const float4*)(WT + (size_t)k3 * HH + col);
        acc[0] += a.x; acc[1] += a.y; acc[2] += a.z; acc[3] += a.w;
        acc[0] += b.x; acc[1] += b.y; acc[2] += b.z; acc[3] += b.w;
        acc[0] += c.x; acc[1] += c.y; acc[2] += c.z; acc[3] += c.w;
        acc[0] += d.x; acc[1] += d.y; acc[2] += d.z; acc[3] += d.w;
    }
    for (; i < cnt; ++i) {
        const int k = sl[i];
        float4 a = *(const float4*)(WT + (size_t)k * HH + col);
        acc[0] += a.x; acc[1] += a.y; acc[2] += a.z; acc[3] += a.w;
    }
}

__device__ __forceinline__ int build_list256(unsigned mask, unsigned short* sl,
                                             int* s_w, int lane, int wid, int col)
{
    int myc = __popc(mask);
    int pre = myc;
#pragma unroll
    for (int o = 1; o < 32; o <<= 1) {
        int u = __shfl_up_sync(FULLMASK, pre, o);
        if (lane >= o) pre += u;
    }
    if (lane == 31) s_w[wid] = pre;
    __syncthreads();
    int base = 0;
    for (int w = 0; w < wid; ++w) base += s_w[w];
    int off = base + pre - myc;
#pragma unroll
    for (int j = 0; j < 4; ++j)
        if (mask & (1u << j)) sl[off++] = (unsigned short)(col + j);
    int ncnt = 0;
#pragma unroll
    for (int w = 0; w < 8; ++w) ncnt += s_w[w];
    __syncthreads();
    return ncnt;
}

// ---------------------------------------------------------------------------
// Head kernel: lif1(0) — reads empty z1 list, updates v1/i1 (+c0), writes z1(0).
// ---------------------------------------------------------------------------
__global__ __launch_bounds__(256)
void lif1_k(const unsigned short* __restrict__ l1r, const int* __restrict__ c1r,
            unsigned short* __restrict__ l1w, int* __restrict__ c1w,
            const float* __restrict__ W1T, const float* __restrict__ c0v,
            float* __restrict__ V, float* __restrict__ I)
{
    __shared__ LifSmem ls;
    const int m = blockIdx.x, tid = threadIdx.x;
    const int lane = tid & 31, wid = tid >> 5;
    const int col = tid * 4;
    const size_t ridx = (size_t)m * HH + col;

    int cnt = c1r[m];
    for (int i = tid; i < cnt; i += 256) ls.la[i] = l1r[(size_t)m * HH + i];
    __syncthreads();

    float acc[4] = {0.f, 0.f, 0.f, 0.f};
    sparse_accum4(acc, W1T, ls.la, cnt, col);

    float4 v4 = *(const float4*)(V + ridx);
    float4 i4 = *(const float4*)(I + ridx);
    float4 q4 = *(const float4*)(c0v + ridx);
    float vo[4] = {v4.x, v4.y, v4.z, v4.w};
    float io[4] = {i4.x, i4.y, i4.z, i4.w};
    float cq[4] = {q4.x, q4.y, q4.z, q4.w};
    float vn[4], in_[4];
    unsigned mask = 0;
#pragma unroll
    for (int j = 0; j < 4; ++j) {
        float vdec = vo[j] + 0.1f * (io[j] - vo[j]);
        float z = (vdec > 1.0f) ? 1.0f : 0.0f;
        vn[j] = (1.0f - z) * vdec;
        float idec = io[j] * 0.8f;
        in_[j] = (idec + cq[j]) + acc[j];
        if (z != 0.0f) mask |= (1u << j);
    }
    *(float4*)(V + ridx) = make_float4(vn[0], vn[1], vn[2], vn[3]);
    *(float4*)(I + ridx) = make_float4(in_[0], in_[1], in_[2], in_[3]);

    __syncthreads();
    int ncnt = build_list256(mask, ls.lb, ls.sw, lane, wid, col);
    for (int i = tid; i < ncnt; i += 256) l1w[(size_t)m * HH + i] = ls.lb[i];
    if (tid == 0) c1w[m] = ncnt;
}

// ---------------------------------------------------------------------------
// Merged step: one block per batch row m does
//   lif2(t): acc = gather(WcT, z1(t)) + bc + gather(w2T, z2(t-1)); v2/i2 update;
//            optional z-store to out (t=15 only); rebuild z2 list; count.
//   lif1(t+1) (if do_lif1): gather(W1T, z1(t)); v1/i1 update (+c0); write z1(t+1).
// z1(t) list loaded once and shared. All chains identical to R14 (bitwise).
// ---------------------------------------------------------------------------
__global__ __launch_bounds__(256)
void merged_step(const unsigned short* __restrict__ l1r, const int* __restrict__ c1r,
                 unsigned short* __restrict__ l1w, int* __restrict__ c1w,
                 unsigned short* __restrict__ l2, int* __restrict__ c2,
                 const float* __restrict__ W1T, const float* __restrict__ WcT,
                 const float* __restrict__ W2T,
                 const float* __restrict__ bc, const float* __restrict__ c0v,
                 float* __restrict__ v1, float* __restrict__ i1,
                 float* __restrict__ v2, float* __restrict__ i2,
                 float* __restrict__ zout, unsigned* __restrict__ cnt_out,
                 int do_lif1)
{
    __shared__ LifSmem ls;
    const int m = blockIdx.x, tid = threadIdx.x;
    const int lane = tid & 31, wid = tid >> 5;
    const int col = tid * 4;
    const size_t ridx = (size_t)m * HH + col;

    const int cnt1 = c1r[m];
    const int cnt2 = c2[m];
    for (int i = tid; i < cnt1; i += 256) ls.la[i] = l1r[(size_t)m * HH + i];
    for (int i = tid; i < cnt2; i += 256) ls.lb[i] = l2[(size_t)m * HH + i];
    __syncthreads();

    // ---- lif2(t) accumulation (Wc fold — proven in R14) ----
    float acc2[4] = {0.f, 0.f, 0.f, 0.f};
    sparse_accum4(acc2, WcT, ls.la, cnt1, col);    // z1(t) @ Wc^T
    float4 b4 = *(const float4*)(bc + col);
    acc2[0] += b4.x; acc2[1] += b4.y; acc2[2] += b4.z; acc2[3] += b4.w;
    sparse_accum4(acc2, W2T, ls.lb, cnt2, col);    // z2(t-1) @ w2rec^T

    // ---- lif1(t+1) accumulation (same z1(t) list) ----
    float acc1[4] = {0.f, 0.f, 0.f, 0.f};
    if (do_lif1) sparse_accum4(acc1, W1T, ls.la, cnt1, col);

    // ---- lif2 epilogue ----
    {
        float4 v4 = *(const float4*)(v2 + ridx);
        float4 i4 = *(const float4*)(i2 + ridx);
        float vo[4] = {v4.x, v4.y, v4.z, v4.w};
        float io[4] = {i4.x, i4.y, i4.z, i4.w};
        float vn[4], in_[4], zn[4];
        unsigned mask = 0;
#pragma unroll
        for (int j = 0; j < 4; ++j) {
            float vdec = vo[j] + 0.1f * (io[j] - vo[j]);
            float z = (vdec > 1.0f) ? 1.0f : 0.0f;
            vn[j] = (1.0f - z) * vdec;
            float idec = io[j] * 0.8f;
            in_[j] = idec + acc2[j];
            zn[j] = z;
            if (z != 0.0f) mask |= (1u << j);
        }
        *(float4*)(v2 + ridx) = make_float4(vn[0], vn[1], vn[2], vn[3]);
        *(float4*)(i2 + ridx) = make_float4(in_[0], in_[1], in_[2], in_[3]);
        if (zout)
            *(float4*)(zout + ridx) = make_float4(zn[0], zn[1], zn[2], zn[3]);

        __syncthreads();                       // lists fully consumed
        int ncnt = build_list256(mask, ls.lb, ls.sw, lane, wid, col);
        for (int i = tid; i < ncnt; i += 256) l2[(size_t)m * HH + i] = ls.lb[i];
        if (tid == 0) {
            c2[m] = ncnt;
            atomicAdd(cnt_out, (unsigned)ncnt);
        }
    }

    // ---- lif1(t+1) epilogue ----
    if (do_lif1) {
        float4 v4 = *(const float4*)(v1 + ridx);
        float4 i4 = *(const float4*)(i1 + ridx);
        float4 q4 = *(const float4*)(c0v + ridx);
        float vo[4] = {v4.x, v4.y, v4.z, v4.w};
        float io[4] = {i4.x, i4.y, i4.z, i4.w};
        float cq[4] = {q4.x, q4.y, q4.z, q4.w};
        float vn[4], in_[4];
        unsigned mask = 0;
#pragma unroll
        for (int j = 0; j < 4; ++j) {
            float vdec = vo[j] + 0.1f * (io[j] - vo[j]);
            float z = (vdec > 1.0f) ? 1.0f : 0.0f;
            vn[j] = (1.0f - z) * vdec;
            float idec = io[j] * 0.8f;
            in_[j] = (idec + cq[j]) + acc1[j];
            if (z != 0.0f) mask |= (1u << j);
        }
        *(float4*)(v1 + ridx) = make_float4(vn[0], vn[1], vn[2], vn[3]);
        *(float4*)(i1 + ridx) = make_float4(in_[0], in_[1], in_[2], in_[3]);

        __syncthreads();
        int ncnt = build_list256(mask, ls.la, ls.sw, lane, wid, col);
        for (int i = tid; i < ncnt; i += 256) l1w[(size_t)m * HH + i] = ls.la[i];
        if (tid == 0) c1w[m] = ncnt;
    }
}

// ---------------------------------------------------------------------------
__global__ void finalize_scalar(const unsigned* __restrict__ cnt,
                                float* __restrict__ out, int n, int out_size)
{
    if (threadIdx.x == 0 && blockIdx.x == 0 && out_size > n) {
        float rs = 0.f;
        for (int t = 0; t < TW; ++t)
            rs += (float)cnt[t] * (1.0f / 4194304.0f);   // exact: /2^22
        out[n] = rs * (1.0f / 16.0f);                     // inv_T, exact
    }
}

// ---------------------------------------------------------------------------
extern "C" void kernel_launch(void* const* d_in, const int* in_sizes, int n_in,
                              void* d_out, int out_size)
{
    const float* x     = (const float*)d_in[0];
    const float* fc1w  = (const float*)d_in[1];
    const float* fc1b  = (const float*)d_in[2];
    const float* w1in  = (const float*)d_in[3];
    const float* w1rec = (const float*)d_in[4];
    const float* fc2w  = (const float*)d_in[5];
    const float* fc2b  = (const float*)d_in[6];
    const float* w2in  = (const float*)d_in[7];
    const float* w2rec = (const float*)d_in[8];
    (void)in_sizes; (void)n_in;

    float *z0, *c0, *v1, *i1, *v2, *i2, *w1T, *f2T, *w2T, *Wc, *WcT, *bc;
    unsigned short *l1[2], *l2;
    int *c1[2], *c2;
    unsigned* cnt;
    cudaGetSymbolAddress((void**)&z0, g_z0);
    cudaGetSymbolAddress((void**)&c0, g_c0);
    cudaGetSymbolAddress((void**)&v1, g_v1);
    cudaGetSymbolAddress((void**)&i1, g_i1);
    cudaGetSymbolAddress((void**)&v2, g_v2);
    cudaGetSymbolAddress((void**)&i2, g_i2);
    cudaGetSymbolAddress((void**)&w1T, g_w1T);
    cudaGetSymbolAddress((void**)&f2T, g_f2T);
    cudaGetSymbolAddress((void**)&w2T, g_w2T);
    cudaGetSymbolAddress((void**)&Wc, g_Wc);
    cudaGetSymbolAddress((void**)&WcT, g_WcT);
    cudaGetSymbolAddress((void**)&bc, g_bc);
    {
        unsigned short* p;
        cudaGetSymbolAddress((void**)&p, g_l1);
        l1[0] = p; l1[1] = p + NEL;
        cudaGetSymbolAddress((void**)&l2, g_l2);
        int* q;
        cudaGetSymbolAddress((void**)&q, g_c1);
        c1[0] = q; c1[1] = q + BSZ;
        cudaGetSymbolAddress((void**)&c2, g_c2);
    }
    cudaGetSymbolAddress((void**)&cnt, g_cnt);

    dim3 gbig(HH / BN, BSZ / BM);   // (8, 32)
    dim3 ghh(HH / BN, HH / BM);     // (8, 8)
    dim3 tgrid(32, 32), tblk(32, 8);

    init_state<<<256, 256>>>();

    // ---- one-time prologue (R14's proven form: NO c0 fold) ----
    sgemm0<<<gbig, 256>>>(x, fc1w, fc1b, z0, DD, HH);     // z0 = fc1(x)
    sgemm0<<<gbig, 256>>>(z0, w1in, nullptr, c0, HH, HH); // c0 = z0@w1in^T
    transpose_hh<<<tgrid, tblk>>>(w1rec, w1T);
    transpose_hh<<<tgrid, tblk>>>(fc2w,  f2T);
    transpose_hh<<<tgrid, tblk>>>(w2rec, w2T);
    sgemm0<<<ghh, 256>>>(w2in, f2T, nullptr, Wc, HH, HH); // Wc = w2in@fc2w
    transpose_hh<<<tgrid, tblk>>>(Wc, WcT);
    bias_prop<<<HH, 256>>>(w2in, fc2b, bc);               // bc = w2in@fc2b

    // ---- pipeline head: lif1(0): reads l1[1] (empty), writes l1[0] ----
    lif1_k<<<LIF_BLKS, 256>>>(l1[1], c1[1], l1[0], c1[0], w1T, c0, v1, i1);

    // ---- merged loop: {lif2(t), lif1(t+1)} per block ----
    for (int t = 0; t < TW; ++t) {
        merged_step<<<LIF_BLKS, 256>>>(
            l1[t & 1], c1[t & 1],             // z1(t) list
            l1[(t + 1) & 1], c1[(t + 1) & 1], // z1(t+1) list (written)
            l2, c2,
            w1T, WcT, w2T, bc, c0,
            v1, i1, v2, i2,
            (t == TW - 1) ? (float*)d_out : nullptr,   // z store only at t=15
            cnt + t,
            (t < TW - 1) ? 1 : 0);
    }

    finalize_scalar<<<1, 32>>>(cnt, (float*)d_out, NEL, out_size);
}

// round 17
// speedup vs baseline: 1.0663x; 1.0663x over previous
#include <cuda_runtime.h>
#include <cstdint>

#define BSZ 4096
#define DD  512
#define HH  1024
#define TW  16
#define NEL (BSZ * HH)

#define BM 128
#define BN 128
#define BK 16
#define TM 8
#define TN 8
#define FULLMASK 0xFFFFFFFFu

#define LIF_BLKS 4096
#define TR_BLKS  1024            // (HH/32)^2

// ---------------------------------------------------------------------------
// Device scratch
// ---------------------------------------------------------------------------
__device__ float g_z0[NEL];           // fc1(x)
__device__ float g_c0[NEL];           // z0 @ w1in^T (time-invariant LIF1 input)
__device__ float g_v1[NEL], g_i1[NEL];
__device__ float g_v2[NEL], g_i2[NEL];
__device__ float g_w1T[HH * HH];      // w1rec^T
__device__ float g_f2T[HH * HH];      // fc2w^T
__device__ float g_w2T[HH * HH];      // w2rec^T
__device__ float g_Wc[HH * HH];       // w2in @ fc2w
__device__ float g_WcT[HH * HH];      // Wc^T
__device__ float g_bc[HH];            // w2in @ fc2b
__device__ unsigned short g_l1[2][NEL];   // parity-buffered z1 active lists
__device__ unsigned short g_l2[NEL];      // z2 active lists (in-place)
__device__ int g_c1[2][BSZ], g_c2[BSZ];
__device__ unsigned g_cnt[TW];

struct LifSmem { unsigned short la[HH]; unsigned short lb[HH]; int sw[8]; };

// ---------------------------------------------------------------------------
__global__ void init_state() {
    size_t i = (size_t)blockIdx.x * blockDim.x + threadIdx.x;
    size_t st = (size_t)gridDim.x * blockDim.x;
    for (size_t k = i; k < (size_t)NEL; k += st) {
        g_v1[k] = 0.f; g_i1[k] = 0.f; g_v2[k] = 0.f; g_i2[k] = 0.f;
    }
    for (size_t k = i; k < (size_t)BSZ; k += st) {
        g_c1[0][k] = 0; g_c1[1][k] = 0; g_c2[k] = 0;
    }
    if (i < TW) g_cnt[i] = 0u;
}

// ---------------------------------------------------------------------------
// GEMM body (proven): C = A @ W^T (+bias), caller-provided smem.
// ---------------------------------------------------------------------------
__device__ __forceinline__ void gemm_body(
    float* __restrict__ Asf, float* __restrict__ Bsf,
    const float* __restrict__ A1, const float* __restrict__ W1,
    const float* __restrict__ bias, float* __restrict__ Cout,
    int K1, int N, int bn, int bm, int tid)
{
    const int tx = tid & 15, ty = tid >> 4;
    const int lrow = tid >> 2, lcol = (tid & 3) << 2;
    #define AS_(b, k, x) Asf[((b) * BK + (k)) * (BM + 4) + (x)]
    #define BS_(b, k, x) Bsf[((b) * BK + (k)) * (BN + 4) + (x)]

    float acc[TM][TN];
#pragma unroll
    for (int i = 0; i < TM; ++i)
#pragma unroll
        for (int j = 0; j < TN; ++j) acc[i][j] = 0.f;

    const int ntot = K1 / BK;
    float4 ra0, ra1, rb0, rb1;

    #define LDGT(kt) do {                                                      \
        const float* Ap = A1 + (size_t)(bm * BM + lrow) * K1 + (kt) * BK + lcol;\
        const float* Wp = W1 + (size_t)(bn * BN + lrow) * K1 + (kt) * BK + lcol;\
        ra0 = *(const float4*)Ap; ra1 = *(const float4*)(Ap + (size_t)64 * K1); \
        rb0 = *(const float4*)Wp; rb1 = *(const float4*)(Wp + (size_t)64 * K1); \
    } while (0)
    #define STST(buf) do {                                                     \
        AS_(buf, lcol + 0, lrow) = ra0.x; AS_(buf, lcol + 1, lrow) = ra0.y;    \
        AS_(buf, lcol + 2, lrow) = ra0.z; AS_(buf, lcol + 3, lrow) = ra0.w;    \
        AS_(buf, lcol + 0, lrow + 64) = ra1.x; AS_(buf, lcol + 1, lrow + 64) = ra1.y; \
        AS_(buf, lcol + 2, lrow + 64) = ra1.z; AS_(buf, lcol + 3, lrow + 64) = ra1.w; \
        BS_(buf, lcol + 0, lrow) = rb0.x; BS_(buf, lcol + 1, lrow) = rb0.y;    \
        BS_(buf, lcol + 2, lrow) = rb0.z; BS_(buf, lcol + 3, lrow) = rb0.w;    \
        BS_(buf, lcol + 0, lrow + 64) = rb1.x; BS_(buf, lcol + 1, lrow + 64) = rb1.y; \
        BS_(buf, lcol + 2, lrow + 64) = rb1.z; BS_(buf, lcol + 3, lrow + 64) = rb1.w; \
    } while (0)

    LDGT(0); STST(0); __syncthreads();
    for (int kt = 0; kt < ntot; ++kt) {
        const int cur = kt & 1;
        const bool more = (kt + 1 < ntot);
        if (more) LDGT(kt + 1);
#pragma unroll
        for (int k = 0; k < BK; ++k) {
            const float4 av0 = *(const float4*)&AS_(cur, k, ty * TM);
            const float4 av1 = *(const float4*)&AS_(cur, k, ty * TM + 4);
            const float4 bv0 = *(const float4*)&BS_(cur, k, tx * TN);
            const float4 bv1 = *(const float4*)&BS_(cur, k, tx * TN + 4);
            float a[TM] = {av0.x, av0.y, av0.z, av0.w, av1.x, av1.y, av1.z, av1.w};
            float b[TN] = {bv0.x, bv0.y, bv0.z, bv0.w, bv1.x, bv1.y, bv1.z, bv1.w};
#pragma unroll
            for (int i = 0; i < TM; ++i)
#pragma unroll
                for (int j = 0; j < TN; ++j) acc[i][j] += a[i] * b[j];
        }
        if (more) { STST(cur ^ 1); __syncthreads(); }
    }
    const int m0 = bm * BM + ty * TM, n0 = bn * BN + tx * TN;
#pragma unroll
    for (int i = 0; i < TM; ++i) {
        size_t row = (size_t)(m0 + i) * N + n0;
#pragma unroll
        for (int j = 0; j < TN; ++j) {
            float v = acc[i][j];
            if (bias) v += bias[n0 + j];
            Cout[row + j] = v;
        }
    }
}

// HxH transpose body, caller smem (needs 32*33 floats)
__device__ __forceinline__ void transpose_body(float* tsm,
    const float* __restrict__ in, float* __restrict__ out, int bid, int tid)
{
    const int bx = bid & 31, by = bid >> 5;
    const int tx = tid & 31, ty = tid >> 5;   // 32 x 8
    #define T_(r, c) tsm[(r) * 33 + (c)]
    int x = bx * 32 + tx, y = by * 32 + ty;
#pragma unroll
    for (int j = 0; j < 32; j += 8)
        T_(ty + j, tx) = in[(size_t)(y + j) * HH + x];
    __syncthreads();
    x = by * 32 + tx; y = bx * 32 + ty;
#pragma unroll
    for (int j = 0; j < 32; j += 8)
        out[(size_t)(y + j) * HH + x] = T_(tx, ty + j);
}

__device__ __forceinline__ void bias_prop_body(float* red,
    const float* __restrict__ Wm, const float* __restrict__ b,
    float* __restrict__ bo, int n, int tid)
{
    float s = 0.f;
    for (int k = tid; k < HH; k += 256) s += Wm[(size_t)n * HH + k] * b[k];
    red[tid] = s; __syncthreads();
    for (int o = 128; o; o >>= 1) {
        if (tid < o) red[tid] += red[tid + o];
        __syncthreads();
    }
    if (tid == 0) bo[n] = red[0];
}

// ---------------------------------------------------------------------------
// Sparse accumulate: acc[j] += WT[k][col+j] over listed k ASCENDING (float4).
// Bitwise equal to dense fp32 FMA chain (z=1 adds w exactly; z=0 no-op).
// ---------------------------------------------------------------------------
__device__ __forceinline__ void sparse_accum4(float acc[4], const float* __restrict__ WT,
                                              const unsigned short* __restrict__ sl,
                                              int cnt, int col)
{
    int i = 0;
    for (; i + 4 <= cnt; i += 4) {
        const int k0 = sl[i], k1 = sl[i + 1], k2 = sl[i + 2], k3 = sl[i + 3];
        float4 a = *(const float4*)(WT + (size_t)k0 * HH + col);
        float4 b = *(const float4*)(WT + (size_t)k1 * HH + col);
        float4 c = *(const float4*)(WT + (size_t)k2 * HH + col);
        float4 d = *(const float4*)(WT + (size_t)k3 * HH + col);
        acc[0] += a.x; acc[1] += a.y; acc[2] += a.z; acc[3] += a.w;
        acc[0] += b.x; acc[1] += b.y; acc[2] += b.z; acc[3] += b.w;
        acc[0] += c.x; acc[1] += c.y; acc[2] += c.z; acc[3] += c.w;
        acc[0] += d.x; acc[1] += d.y; acc[2] += d.z; acc[3] += d.w;
    }
    for (; i < cnt; ++i) {
        const int k = sl[i];
        float4 a = *(const float4*)(WT + (size_t)k * HH + col);
        acc[0] += a.x; acc[1] += a.y; acc[2] += a.z; acc[3] += a.w;
    }
}

__device__ __forceinline__ int build_list256(unsigned mask, unsigned short* sl,
                                             int* s_w, int lane, int wid, int col)
{
    int myc = __popc(mask);
    int pre = myc;
#pragma unroll
    for (int o = 1; o < 32; o <<= 1) {
        int u = __shfl_up_sync(FULLMASK, pre, o);
        if (lane >= o) pre += u;
    }
    if (lane == 31) s_w[wid] = pre;
    __syncthreads();
    int base = 0;
    for (int w = 0; w < wid; ++w) base += s_w[w];
    int off = base + pre - myc;
#pragma unroll
    for (int j = 0; j < 4; ++j)
        if (mask & (1u << j)) sl[off++] = (unsigned short)(col + j);
    int ncnt = 0;
#pragma unroll
    for (int w = 0; w < 8; ++w) ncnt += s_w[w];
    __syncthreads();
    return ncnt;
}

// ---------------------------------------------------------------------------
// LIF bodies (R14-exact arithmetic)
// ---------------------------------------------------------------------------
__device__ __forceinline__ void lif1_body(LifSmem* ls, int m, int tid,
    const unsigned short* __restrict__ l1r, const int* __restrict__ c1r,
    unsigned short* __restrict__ l1w, int* __restrict__ c1w,
    const float* __restrict__ W1T, const float* __restrict__ c0v,
    float* __restrict__ V, float* __restrict__ I)
{
    const int lane = tid & 31, wid = tid >> 5;
    const int col = tid * 4;
    const size_t ridx = (size_t)m * HH + col;

    int cnt = c1r[m];
    for (int i = tid; i < cnt; i += 256) ls->la[i] = l1r[(size_t)m * HH + i];
    __syncthreads();

    float acc[4] = {0.f, 0.f, 0.f, 0.f};
    sparse_accum4(acc, W1T, ls->la, cnt, col);

    float4 v4 = *(const float4*)(V + ridx);
    float4 i4 = *(const float4*)(I + ridx);
    float4 q4 = *(const float4*)(c0v + ridx);
    float vo[4] = {v4.x, v4.y, v4.z, v4.w};
    float io[4] = {i4.x, i4.y, i4.z, i4.w};
    float cq[4] = {q4.x, q4.y, q4.z, q4.w};
    float vn[4], in_[4];
    unsigned mask = 0;
#pragma unroll
    for (int j = 0; j < 4; ++j) {
        float vdec = vo[j] + 0.1f * (io[j] - vo[j]);
        float z = (vdec > 1.0f) ? 1.0f : 0.0f;
        vn[j] = (1.0f - z) * vdec;
        float idec = io[j] * 0.8f;
        in_[j] = (idec + cq[j]) + acc[j];
        if (z != 0.0f) mask |= (1u << j);
    }
    *(float4*)(V + ridx) = make_float4(vn[0], vn[1], vn[2], vn[3]);
    *(float4*)(I + ridx) = make_float4(in_[0], in_[1], in_[2], in_[3]);

    __syncthreads();
    int ncnt = build_list256(mask, ls->lb, ls->sw, lane, wid, col);
    for (int i = tid; i < ncnt; i += 256) l1w[(size_t)m * HH + i] = ls->lb[i];
    if (tid == 0) c1w[m] = ncnt;
}

__device__ __forceinline__ void lif2_body(LifSmem* ls, int m, int tid,
    const unsigned short* __restrict__ l1r, const int* __restrict__ c1r,
    unsigned short* __restrict__ l2, int* __restrict__ c2,
    const float* __restrict__ WcT, const float* __restrict__ W2T,
    const float* __restrict__ bc,
    float* __restrict__ V, float* __restrict__ I,
    float* __restrict__ zout, unsigned* __restrict__ cnt_out)
{
    const int lane = tid & 31, wid = tid >> 5;
    const int col = tid * 4;
    const size_t ridx = (size_t)m * HH + col;

    int cnt1 = c1r[m];
    int cnt2 = c2[m];
    for (int i = tid; i < cnt1; i += 256) ls->la[i] = l1r[(size_t)m * HH + i];
    for (int i = tid; i < cnt2; i += 256) ls->lb[i] = l2[(size_t)m * HH + i];
    __syncthreads();

    float acc[4] = {0.f, 0.f, 0.f, 0.f};
    sparse_accum4(acc, WcT, ls->la, cnt1, col);    // z1(t) @ Wc^T
    float4 b4 = *(const float4*)(bc + col);
    acc[0] += b4.x; acc[1] += b4.y; acc[2] += b4.z; acc[3] += b4.w;
    sparse_accum4(acc, W2T, ls->lb, cnt2, col);    // z2(t-1) @ w2rec^T

    float4 v4 = *(const float4*)(V + ridx);
    float4 i4 = *(const float4*)(I + ridx);
    float vo[4] = {v4.x, v4.y, v4.z, v4.w};
    float io[4] = {i4.x, i4.y, i4.z, i4.w};
    float vn[4], in_[4], zn[4];
    unsigned mask = 0;
#pragma unroll
    for (int j = 0; j < 4; ++j) {
        float vdec = vo[j] + 0.1f * (io[j] - vo[j]);
        float z = (vdec > 1.0f) ? 1.0f : 0.0f;
        vn[j] = (1.0f - z) * vdec;
        float idec = io[j] * 0.8f;
        in_[j] = idec + acc[j];
        zn[j] = z;
        if (z != 0.0f) mask |= (1u << j);
    }
    *(float4*)(V + ridx) = make_float4(vn[0], vn[1], vn[2], vn[3]);
    *(float4*)(I + ridx) = make_float4(in_[0], in_[1], in_[2], in_[3]);
    if (zout)
        *(float4*)(zout + ridx) = make_float4(zn[0], zn[1], zn[2], zn[3]);

    __syncthreads();
    int ncnt = build_list256(mask, ls->lb, ls->sw, lane, wid, col);
    for (int i = tid; i < ncnt; i += 256) l2[(size_t)m * HH + i] = ls->lb[i];
    if (tid == 0) {
        c2[m] = ncnt;
        atomicAdd(cnt_out, (unsigned)ncnt);
    }
}

// ---------------------------------------------------------------------------
// Prologue phase kernels (heterogeneous block roles; 256 threads each)
// ---------------------------------------------------------------------------
#define GEMM_SMEM_FLOATS (4 * BK * (BM + 4))

// Phase A: [0,256) z0 GEMM; then 3 x 1024 transposes (w1T, f2T, w2T)
__global__ __launch_bounds__(256)
void phaseA(const float* __restrict__ x, const float* __restrict__ fc1w,
            const float* __restrict__ fc1b, float* __restrict__ z0,
            const float* __restrict__ w1rec, float* __restrict__ w1T,
            const float* __restrict__ fc2w, float* __restrict__ f2T,
            const float* __restrict__ w2rec, float* __restrict__ w2T)
{
    __shared__ __align__(16) float sm[GEMM_SMEM_FLOATS];
    const int bid = blockIdx.x, tid = threadIdx.x;
    if (bid < 256) {
        gemm_body(sm, sm + GEMM_SMEM_FLOATS / 2, x, fc1w, fc1b, z0,
                  DD, HH, bid & 7, bid >> 3, tid);
    } else if (bid < 256 + TR_BLKS) {
        transpose_body(sm, w1rec, w1T, bid - 256, tid);
    } else if (bid < 256 + 2 * TR_BLKS) {
        transpose_body(sm, fc2w, f2T, bid - 256 - TR_BLKS, tid);
    } else {
        transpose_body(sm, w2rec, w2T, bid - 256 - 2 * TR_BLKS, tid);
    }
}

// Phase B: [0,256) c0 GEMM; [256,320) Wc GEMM; [320,320+1024) bias_prop
__global__ __launch_bounds__(256)
void phaseB(const float* __restrict__ z0, const float* __restrict__ w1in,
            float* __restrict__ c0,
            const float* __restrict__ w2in, const float* __restrict__ f2T,
            float* __restrict__ Wc,
            const float* __restrict__ fc2b, float* __restrict__ bc)
{
    __shared__ __align__(16) float sm[GEMM_SMEM_FLOATS];
    const int bid = blockIdx.x, tid = threadIdx.x;
    if (bid < 256) {
        gemm_body(sm, sm + GEMM_SMEM_FLOATS / 2, z0, w1in, nullptr, c0,
                  HH, HH, bid & 7, bid >> 3, tid);
    } else if (bid < 320) {
        const int b = bid - 256;       // 64 blocks: 8 x 8
        gemm_body(sm, sm + GEMM_SMEM_FLOATS / 2, w2in, f2T, nullptr, Wc,
                  HH, HH, b & 7, b >> 3, tid);
    } else {
        bias_prop_body(sm, w2in, fc2b, bc, bid - 320, tid);
    }
}

// Phase C: [0,4096) lif1(0) head; [4096,5120) WcT transpose
__global__ __launch_bounds__(256)
void phaseC(const unsigned short* __restrict__ l1r, const int* __restrict__ c1r,
            unsigned short* __restrict__ l1w, int* __restrict__ c1w,
            const float* __restrict__ W1T, const float* __restrict__ c0v,
            float* __restrict__ v1, float* __restrict__ i1,
            const float* __restrict__ Wc, float* __restrict__ WcT)
{
    __shared__ __align__(16) unsigned char sm[sizeof(LifSmem) > 32 * 33 * 4
                                              ? sizeof(LifSmem) : 32 * 33 * 4];
    const int bid = blockIdx.x, tid = threadIdx.x;
    if (bid < LIF_BLKS) {
        lif1_body((LifSmem*)sm, bid, tid, l1r, c1r, l1w, c1w, W1T, c0v, v1, i1);
    } else {
        transpose_body((float*)sm, Wc, WcT, bid - LIF_BLKS, tid);
    }
}

// ---------------------------------------------------------------------------
// Fused loop step (R14-exact): [0,4096) lif2(t); [4096,8192) lif1(t+1)
// ---------------------------------------------------------------------------
__global__ __launch_bounds__(256)
void fused_step(const unsigned short* __restrict__ l1r, const int* __restrict__ c1r,
                unsigned short* __restrict__ l1w, int* __restrict__ c1w,
                unsigned short* __restrict__ l2, int* __restrict__ c2,
                const float* __restrict__ W1T, const float* __restrict__ WcT,
                const float* __restrict__ W2T, const float* __restrict__ bc,
                const float* __restrict__ c0v,
                float* __restrict__ v1, float* __restrict__ i1,
                float* __restrict__ v2, float* __restrict__ i2,
                float* __restrict__ zout, unsigned* __restrict__ cnt_out,
                int do_lif1)
{
    __shared__ LifSmem ls;
    const int bid = blockIdx.x, tid = threadIdx.x;
    if (bid < LIF_BLKS) {
        lif2_body(&ls, bid, tid, l1r, c1r, l2, c2, WcT, W2T, bc, v2, i2,
                  zout, cnt_out);
    } else if (do_lif1) {
        lif1_body(&ls, bid - LIF_BLKS, tid, l1r, c1r, l1w, c1w, W1T, c0v, v1, i1);
    }
}

// ---------------------------------------------------------------------------
__global__ void finalize_scalar(const unsigned* __restrict__ cnt,
                                float* __restrict__ out, int n, int out_size)
{
    if (threadIdx.x == 0 && blockIdx.x == 0 && out_size > n) {
        float rs = 0.f;
        for (int t = 0; t < TW; ++t)
            rs += (float)cnt[t] * (1.0f / 4194304.0f);   // exact: /2^22
        out[n] = rs * (1.0f / 16.0f);                     // inv_T, exact
    }
}

// ---------------------------------------------------------------------------
extern "C" void kernel_launch(void* const* d_in, const int* in_sizes, int n_in,
                              void* d_out, int out_size)
{
    const float* x     = (const float*)d_in[0];
    const float* fc1w  = (const float*)d_in[1];
    const float* fc1b  = (const float*)d_in[2];
    const float* w1in  = (const float*)d_in[3];
    const float* w1rec = (const float*)d_in[4];
    const float* fc2w  = (const float*)d_in[5];
    const float* fc2b  = (const float*)d_in[6];
    const float* w2in  = (const float*)d_in[7];
    const float* w2rec = (const float*)d_in[8];
    (void)in_sizes; (void)n_in;

    float *z0, *c0, *v1, *i1, *v2, *i2, *w1T, *f2T, *w2T, *Wc, *WcT, *bc;
    unsigned short *l1[2], *l2;
    int *c1[2], *c2;
    unsigned* cnt;
    cudaGetSymbolAddress((void**)&z0, g_z0);
    cudaGetSymbolAddress((void**)&c0, g_c0);
    cudaGetSymbolAddress((void**)&v1, g_v1);
    cudaGetSymbolAddress((void**)&i1, g_i1);
    cudaGetSymbolAddress((void**)&v2, g_v2);
    cudaGetSymbolAddress((void**)&i2, g_i2);
    cudaGetSymbolAddress((void**)&w1T, g_w1T);
    cudaGetSymbolAddress((void**)&f2T, g_f2T);
    cudaGetSymbolAddress((void**)&w2T, g_w2T);
    cudaGetSymbolAddress((void**)&Wc, g_Wc);
    cudaGetSymbolAddress((void**)&WcT, g_WcT);
    cudaGetSymbolAddress((void**)&bc, g_bc);
    {
        unsigned short* p;
        cudaGetSymbolAddress((void**)&p, g_l1);
        l1[0] = p; l1[1] = p + NEL;
        cudaGetSymbolAddress((void**)&l2, g_l2);
        int* q;
        cudaGetSymbolAddress((void**)&q, g_c1);
        c1[0] = q; c1[1] = q + BSZ;
        cudaGetSymbolAddress((void**)&c2, g_c2);
    }
    cudaGetSymbolAddress((void**)&cnt, g_cnt);

    init_state<<<256, 256>>>();

    // ---- prologue: 3 overlapped phases ----
    phaseA<<<256 + 3 * TR_BLKS, 256>>>(x, fc1w, fc1b, z0,
                                       w1rec, w1T, fc2w, f2T, w2rec, w2T);
    phaseB<<<320 + HH, 256>>>(z0, w1in, c0, w2in, f2T, Wc, fc2b, bc);
    phaseC<<<LIF_BLKS + TR_BLKS, 256>>>(l1[1], c1[1], l1[0], c1[0],
                                        w1T, c0, v1, i1, Wc, WcT);

    // ---- fused loop: {lif2(t), lif1(t+1)} in separate blocks (R14 form) ----
    for (int t = 0; t < TW; ++t) {
        fused_step<<<2 * LIF_BLKS, 256>>>(
            l1[t & 1], c1[t & 1],             // z1(t) list
            l1[(t + 1) & 1], c1[(t + 1) & 1], // z1(t+1) list (written)
            l2, c2,
            w1T, WcT, w2T, bc, c0,
            v1, i1, v2, i2,
            (t == TW - 1) ? (float*)d_out : nullptr,   // z store only at t=15
            cnt + t,
            (t < TW - 1) ? 1 : 0);
    }

    finalize_scalar<<<1, 32>>>(cnt, (float*)d_out, NEL, out_size);
}